// round 3
// baseline (speedup 1.0000x reference)
#include <cuda_runtime.h>
#include <math.h>

#define L 8192
#define K 48
#define NODE 128
#define EDGE 128
#define SENTK 0xFFFFFFFFFFFFFFFFULL

// ---------------- device scratch (static; allocation-free) ----------------
__device__ __align__(16) float g_A[L * EDGE];
__device__ __align__(16) float g_B[L * EDGE];
__device__ __align__(16) float g_WpT[EDGE * EDGE];   // [c][n] = Wproj[n][c]*ln_scale[c]
__device__ __align__(16) float g_WsmT[32 * EDGE];    // [q][c] = We[c][128+q]
__device__ __align__(16) float g_w1[EDGE];
__device__ __align__(16) float g_c0[EDGE];
__device__ int   g_knn_idx[L * K];
__device__ float g_knn_d[L * K];

// ---------------- tiny precompute ----------------
__global__ void prep_small_kernel(const float* __restrict__ Wproj,
                                  const float* __restrict__ ln_scale,
                                  const float* __restrict__ ln_bias,
                                  const float* __restrict__ bproj,
                                  const float* __restrict__ We) {
    int tid = threadIdx.x;
    for (int n = tid; n < EDGE * EDGE; n += blockDim.x) {
        int c = n >> 7, t = n & 127;
        g_WpT[n] = Wproj[t * EDGE + c] * ln_scale[c];
    }
    for (int n = tid; n < 32 * EDGE; n += blockDim.x) {
        int q = n >> 7, c = n & 127;
        g_WsmT[n] = We[c * 416 + 128 + q];
    }
    if (tid < EDGE) {
        float s1 = 0.f, s0 = 0.f;
        for (int c = 0; c < EDGE; c++) {
            float w = Wproj[tid * EDGE + c];
            s1 += w * ln_scale[c];
            s0 += w * ln_bias[c];
        }
        g_w1[tid] = s1;
        g_c0[tid] = s0 + bproj[tid];
    }
}

// ---------------- A/B tables ----------------
__global__ void __launch_bounds__(128) prep_ab_kernel(const float* __restrict__ node_h,
                                                      const float* __restrict__ f_node,
                                                      const float* __restrict__ We) {
    __shared__ float nh[32 * 128];
    __shared__ float fn[32 * 128];
    int tid = threadIdx.x;
    int i0 = blockIdx.x * 32;
    for (int f = tid; f < 32 * 128; f += 128) {
        nh[f] = node_h[i0 * 128 + f];
        fn[f] = f_node[i0 * 128 + f];
    }
    __syncthreads();
    const float* WA = We + tid * 416 + 160;   // h_i block
    const float* Wf = We + tid * 416;         // f_node[j] block
    const float* Wh = We + tid * 416 + 288;   // node_h[j] block
    for (int ch = 0; ch < 4; ch++) {
        float a[8], b[8];
#pragma unroll
        for (int ii = 0; ii < 8; ii++) { a[ii] = 0.f; b[ii] = 0.f; }
        for (int c = 0; c < 128; c++) {
            float wa = __ldg(WA + c), wf = __ldg(Wf + c), wh = __ldg(Wh + c);
#pragma unroll
            for (int ii = 0; ii < 8; ii++) {
                int row = ch * 8 + ii;
                float n = nh[row * 128 + c];
                float f = fn[row * 128 + c];
                a[ii] = fmaf(n, wa, a[ii]);
                b[ii] = fmaf(f, wf, fmaf(n, wh, b[ii]));
            }
        }
#pragma unroll
        for (int ii = 0; ii < 8; ii++) {
            g_A[(i0 + ch * 8 + ii) * 128 + tid] = a[ii];
            g_B[(i0 + ch * 8 + ii) * 128 + tid] = b[ii];
        }
    }
}

// ---------------- KNN: one warp per row ----------------
__global__ void __launch_bounds__(256) knn_kernel(const float* __restrict__ X) {
    extern __shared__ float sx[];   // [3][L] SoA
    int tid = threadIdx.x;
    for (int f = tid; f < 3 * L; f += 256) {
        float v = X[f];
        int j = f / 3;
        int d = f - 3 * j;
        sx[d * L + j] = v;
    }
    __syncthreads();
    int lane = tid & 31;
    int i = blockIdx.x * 8 + (tid >> 5);
    float xi = sx[i], yi = sx[L + i], zi = sx[2 * L + i];

    unsigned long long h[8];
#pragma unroll
    for (int m = 0; m < 8; m++) h[m] = SENTK;

    // initial scan: lane-local sorted top-8 of its 256 elements
    for (int s = 0; s < L / 32; s++) {
        int j = lane + (s << 5);
        float dx = xi - sx[j], dy = yi - sx[L + j], dz = zi - sx[2 * L + j];
        float ssq = __fadd_rn(__fadd_rn(__fmul_rn(dx, dx), __fmul_rn(dy, dy)), __fmul_rn(dz, dz));
        unsigned long long key = ((unsigned long long)__float_as_uint(ssq) << 32) | (unsigned int)j;
        if (key < h[7]) {
            h[7] = key;
#pragma unroll
            for (int m = 7; m > 0; m--)
                if (h[m] < h[m - 1]) { unsigned long long t = h[m]; h[m] = h[m - 1]; h[m - 1] = t; }
        }
    }

    unsigned long long mylast = 0ULL;
    for (int r = 0; r < K; r++) {
        if (h[0] == SENTK) {   // rare refill: keys strictly greater than my last emitted
            for (int s = 0; s < L / 32; s++) {
                int j = lane + (s << 5);
                float dx = xi - sx[j], dy = yi - sx[L + j], dz = zi - sx[2 * L + j];
                float ssq = __fadd_rn(__fadd_rn(__fmul_rn(dx, dx), __fmul_rn(dy, dy)), __fmul_rn(dz, dz));
                unsigned long long key = ((unsigned long long)__float_as_uint(ssq) << 32) | (unsigned int)j;
                if (key > mylast && key < h[7]) {
                    h[7] = key;
#pragma unroll
                    for (int m = 7; m > 0; m--)
                        if (h[m] < h[m - 1]) { unsigned long long t = h[m]; h[m] = h[m - 1]; h[m - 1] = t; }
                }
            }
        }
        unsigned long long mn = h[0];
#pragma unroll
        for (int off = 16; off > 0; off >>= 1) {
            unsigned long long o = __shfl_xor_sync(0xffffffffu, mn, off);
            mn = (o < mn) ? o : mn;
        }
        if (h[0] == mn) {      // unique winner (keys unique) pops & writes
            mylast = mn;
#pragma unroll
            for (int m = 0; m < 7; m++) h[m] = h[m + 1];
            h[7] = SENTK;
            g_knn_idx[i * K + r] = (int)(unsigned int)(mn & 0xFFFFFFFFULL);
            float ssq = __uint_as_float((unsigned int)(mn >> 32));
            g_knn_d[i * K + r] = sqrtf(ssq + 1e-6f);
        }
    }
}

// ---------------- main: features + 32-dim contraction + LN-folded projection ----------------
__global__ void __launch_bounds__(128) main_kernel(const float* __restrict__ X,
                                                   const float* __restrict__ Wpos,
                                                   const float* __restrict__ bpos,
                                                   const int* __restrict__ aatype,
                                                   const int* __restrict__ resi,
                                                   float* __restrict__ out) {
    extern __shared__ float sm[];
    float* sWpT   = sm;               // 16384 floats
    float* sE     = sm + 16384;       // 48*132 = 6336   e[k][c], stride 132
    float* sSmall = sm + 22720;       // 48*32 = 1536    [k][q] : e_pos(16) + rbf(16)
    float* sA     = sm + 24256;       // 128
    float* sw1    = sm + 24384;       // 128
    float* sc0    = sm + 24512;       // 128
    float* sMean  = sm + 24640;       // 48
    float* sRstd  = sm + 24688;       // 48
    int*   sJ     = (int*)(sm + 24736); // 48
    float* sD     = sm + 24784;       // 48  (total 24832 floats = 99328 B)

    int tid = threadIdx.x;
    int i = blockIdx.x;

    {
        const float4* src = (const float4*)g_WpT;
        float4* dst = (float4*)sWpT;
#pragma unroll
        for (int n = 0; n < 32; n++) dst[tid + n * 128] = src[tid + n * 128];
        if (tid < 32) ((float4*)sA)[tid] = ((const float4*)(g_A + i * 128))[tid];
        sw1[tid] = g_w1[tid];
        sc0[tid] = g_c0[tid];
        if (tid < K) { sJ[tid] = g_knn_idx[i * K + tid]; sD[tid] = g_knn_d[i * K + tid]; }
    }
    __syncthreads();

    // ---- Phase A: per-edge features + e_pos (thread k) ----
    if (tid < K) {
        int k = tid;
        int j = sJ[k];
        float d = sD[k];
        float rb[16];
#pragma unroll
        for (int q = 0; q < 16; q++) {
            float mu = 2.0f + (20.0f / 15.0f) * (float)q;
            float t = (d - mu) * 0.8f;       // /sigma, sigma=1.25
            rb[q] = expf(-t * t);
            sSmall[k * 32 + 16 + q] = rb[q];
        }
        float gm[8];
        gm[0] = d * 0.1f;
        gm[1] = 1.0f / (1.0f + d);
        gm[2] = expf(-d);
        gm[3] = sinf(d);
        gm[4] = cosf(d);
        float inv = 1.0f / (d + 1e-6f);
        float xs = X[3 * i], ys = X[3 * i + 1], zs = X[3 * i + 2];
        gm[5] = (X[3 * j] - xs) * inv;
        gm[6] = (X[3 * j + 1] - ys) * inv;
        gm[7] = (X[3 * j + 2] - zs) * inv;
        int off = resi[j] - resi[i];
        int p = min(max(off + 8, 0), 15);
        int aa = aatype[j];
#pragma unroll
        for (int r = 0; r < 16; r++) {
            const float* wr = Wpos + r * 66;
            float acc = bpos[r] + __ldg(wr + p) + __ldg(wr + 40 + aa);
#pragma unroll
            for (int q = 0; q < 16; q++) acc = fmaf(rb[q], __ldg(wr + 16 + q), acc);
#pragma unroll
            for (int g = 0; g < 8; g++) acc = fmaf(gm[g], __ldg(wr + 32 + g), acc);
            sSmall[k * 32 + r] = acc;
        }
    }
    __syncthreads();

    // ---- Phase B: e[k][c] = A[c] + B[j_k][c] + WsmT[:,c] . small[k,:] ----
    {
        int c = tid;
        float wreg[32];
#pragma unroll
        for (int q = 0; q < 32; q++) wreg[q] = g_WsmT[q * 128 + c];
        float a = sA[c];
        for (int k0 = 0; k0 < K; k0 += 4) {
            float acc[4];
#pragma unroll
            for (int kk = 0; kk < 4; kk++)
                acc[kk] = a + g_B[sJ[k0 + kk] * 128 + c];
#pragma unroll
            for (int q4 = 0; q4 < 8; q4++) {
#pragma unroll
                for (int kk = 0; kk < 4; kk++) {
                    float4 s4 = *(const float4*)(sSmall + (k0 + kk) * 32 + q4 * 4);
                    acc[kk] = fmaf(s4.x, wreg[q4 * 4 + 0], acc[kk]);
                    acc[kk] = fmaf(s4.y, wreg[q4 * 4 + 1], acc[kk]);
                    acc[kk] = fmaf(s4.z, wreg[q4 * 4 + 2], acc[kk]);
                    acc[kk] = fmaf(s4.w, wreg[q4 * 4 + 3], acc[kk]);
                }
            }
#pragma unroll
            for (int kk = 0; kk < 4; kk++) sE[(k0 + kk) * 132 + c] = acc[kk];
        }
    }
    __syncthreads();

    // ---- LN stats per edge ----
    if (tid < K) {
        int k = tid;
        float s = 0.f, ss = 0.f;
        for (int c = 0; c < 128; c++) {
            float v = sE[k * 132 + c];
            s += v;
            ss = fmaf(v, v, ss);
        }
        float mean = s * (1.0f / 128.0f);
        float var = ss * (1.0f / 128.0f) - mean * mean;
        sMean[k] = mean;
        sRstd[k] = rsqrtf(var + 1e-5f);
    }
    __syncthreads();

    // ---- Phase C: projection GEMM, 6k x 8n register tile per thread ----
    {
        int kg = tid >> 4;       // 0..7
        int ng = tid & 15;       // 0..15
        int k0 = kg * 6;
        int n0 = ng * 8;
        float acc[6][8];
#pragma unroll
        for (int kk = 0; kk < 6; kk++)
#pragma unroll
            for (int nn = 0; nn < 8; nn++) acc[kk][nn] = 0.f;

        for (int c = 0; c < 128; c++) {
            float4 w0 = *(const float4*)(sWpT + c * 128 + n0);
            float4 w1v = *(const float4*)(sWpT + c * 128 + n0 + 4);
            float ev[6];
#pragma unroll
            for (int kk = 0; kk < 6; kk++) ev[kk] = sE[(k0 + kk) * 132 + c];
#pragma unroll
            for (int kk = 0; kk < 6; kk++) {
                acc[kk][0] = fmaf(ev[kk], w0.x, acc[kk][0]);
                acc[kk][1] = fmaf(ev[kk], w0.y, acc[kk][1]);
                acc[kk][2] = fmaf(ev[kk], w0.z, acc[kk][2]);
                acc[kk][3] = fmaf(ev[kk], w0.w, acc[kk][3]);
                acc[kk][4] = fmaf(ev[kk], w1v.x, acc[kk][4]);
                acc[kk][5] = fmaf(ev[kk], w1v.y, acc[kk][5]);
                acc[kk][6] = fmaf(ev[kk], w1v.z, acc[kk][6]);
                acc[kk][7] = fmaf(ev[kk], w1v.w, acc[kk][7]);
            }
        }
#pragma unroll
        for (int kk = 0; kk < 6; kk++) {
            int k = k0 + kk;
            float mean = sMean[k], rstd = sRstd[k];
            float4 o0, o1;
            o0.x = fmaf(rstd, acc[kk][0] - mean * sw1[n0 + 0], sc0[n0 + 0]);
            o0.y = fmaf(rstd, acc[kk][1] - mean * sw1[n0 + 1], sc0[n0 + 1]);
            o0.z = fmaf(rstd, acc[kk][2] - mean * sw1[n0 + 2], sc0[n0 + 2]);
            o0.w = fmaf(rstd, acc[kk][3] - mean * sw1[n0 + 3], sc0[n0 + 3]);
            o1.x = fmaf(rstd, acc[kk][4] - mean * sw1[n0 + 4], sc0[n0 + 4]);
            o1.y = fmaf(rstd, acc[kk][5] - mean * sw1[n0 + 5], sc0[n0 + 5]);
            o1.z = fmaf(rstd, acc[kk][6] - mean * sw1[n0 + 6], sc0[n0 + 6]);
            o1.w = fmaf(rstd, acc[kk][7] - mean * sw1[n0 + 7], sc0[n0 + 7]);
            float* op = out + ((size_t)i * K + k) * 128 + n0;
            *(float4*)op = o0;
            *(float4*)(op + 4) = o1;
        }
    }
}

// ---------------- launch ----------------
extern "C" void kernel_launch(void* const* d_in, const int* in_sizes, int n_in,
                              void* d_out, int out_size) {
    const float* X        = (const float*)d_in[0];
    const float* node_h   = (const float*)d_in[1];
    const float* f_node   = (const float*)d_in[2];
    const float* Wpos     = (const float*)d_in[3];
    const float* bpos     = (const float*)d_in[4];
    const float* We       = (const float*)d_in[5];
    const float* ln_scale = (const float*)d_in[6];
    const float* ln_bias  = (const float*)d_in[7];
    const float* Wproj    = (const float*)d_in[8];
    const float* bproj    = (const float*)d_in[9];
    const int*   aatype   = (const int*)d_in[10];
    const int*   resi     = (const int*)d_in[11];
    float* out = (float*)d_out;

    cudaFuncSetAttribute(knn_kernel, cudaFuncAttributeMaxDynamicSharedMemorySize, 3 * L * 4);
    cudaFuncSetAttribute(main_kernel, cudaFuncAttributeMaxDynamicSharedMemorySize, 99328);

    prep_small_kernel<<<1, 256>>>(Wproj, ln_scale, ln_bias, bproj, We);
    prep_ab_kernel<<<L / 32, 128>>>(node_h, f_node, We);
    knn_kernel<<<L / 8, 256, 3 * L * 4>>>(X);
    main_kernel<<<L, 128, 99328>>>(X, Wpos, bpos, aatype, resi, out);
}

// round 4
// speedup vs baseline: 1.3184x; 1.3184x over previous
#include <cuda_runtime.h>
#include <math.h>

#define L 8192
#define K 48
#define SENTK 0xFFFFFFFFFFFFFFFFULL
typedef unsigned long long ull;

// ---------------- device scratch (static; allocation-free) ----------------
__device__ __align__(16) float g_A[L * 128];
__device__ __align__(16) float g_B[L * 128];
__device__ __align__(16) float g_WpT[128 * 128];   // [c][n] = Wproj[n][c]*ln_scale[c]
__device__ __align__(16) float g_Wsm2[128 * 32];   // [c][q] = We[c][128+q]
__device__ __align__(16) float g_WAT[128 * 128];   // [c][t] = We[t][160+c]
__device__ __align__(16) float g_WfT[128 * 128];   // [c][t] = We[t][c]
__device__ __align__(16) float g_WhT[128 * 128];   // [c][t] = We[t][288+c]
__device__ __align__(16) float g_w1[128];
__device__ __align__(16) float g_c0[128];
__device__ int   g_knn_idx[L * K];
__device__ float g_knn_d[L * K];

__device__ __forceinline__ ull fma2(ull a, ull b, ull c) {
    ull d;
    asm("fma.rn.f32x2 %0, %1, %2, %3;" : "=l"(d) : "l"(a), "l"(b), "l"(c));
    return d;
}
__device__ __forceinline__ ull pack2(float lo, float hi) {
    ull d;
    asm("mov.b64 %0, {%1, %2};" : "=l"(d) : "r"(__float_as_uint(lo)), "r"(__float_as_uint(hi)));
    return d;
}
__device__ __forceinline__ float lo2(ull v) { return __uint_as_float((unsigned)v); }
__device__ __forceinline__ float hi2(ull v) { return __uint_as_float((unsigned)(v >> 32)); }

// ---------------- tiny precompute (transposes + LN folding) ----------------
__global__ void prep_small_kernel(const float* __restrict__ Wproj,
                                  const float* __restrict__ ln_scale,
                                  const float* __restrict__ ln_bias,
                                  const float* __restrict__ bproj,
                                  const float* __restrict__ We) {
    int gid = blockIdx.x * blockDim.x + threadIdx.x;
    int NT = gridDim.x * blockDim.x;
    for (int n = gid; n < 16384; n += NT) {
        int c = n >> 7, t = n & 127;
        g_WpT[n] = Wproj[t * 128 + c] * ln_scale[c];
        g_WAT[n] = We[t * 416 + 160 + c];
        g_WfT[n] = We[t * 416 + c];
        g_WhT[n] = We[t * 416 + 288 + c];
    }
    for (int n = gid; n < 4096; n += NT) {
        int c = n >> 5, q = n & 31;
        g_Wsm2[n] = We[c * 416 + 128 + q];
    }
    if (gid < 128) {
        float s1 = 0.f, s0 = 0.f;
        for (int c = 0; c < 128; c++) {
            float w = Wproj[gid * 128 + c];
            s1 += w * ln_scale[c];
            s0 += w * ln_bias[c];
        }
        g_w1[gid] = s1;
        g_c0[gid] = s0 + bproj[gid];
    }
}

// ---------------- A/B tables (coalesced weight reads) ----------------
__global__ void __launch_bounds__(128) prep_ab_kernel(const float* __restrict__ node_h,
                                                      const float* __restrict__ f_node) {
    __shared__ float nh[32 * 128];
    __shared__ float fn[32 * 128];
    int tid = threadIdx.x;
    int i0 = blockIdx.x * 32;
    for (int f = tid; f < 32 * 128; f += 128) {
        nh[f] = node_h[i0 * 128 + f];
        fn[f] = f_node[i0 * 128 + f];
    }
    __syncthreads();
    for (int ch = 0; ch < 4; ch++) {
        float a[8], b[8];
#pragma unroll
        for (int ii = 0; ii < 8; ii++) { a[ii] = 0.f; b[ii] = 0.f; }
#pragma unroll 4
        for (int c = 0; c < 128; c++) {
            float wa = __ldg(g_WAT + c * 128 + tid);
            float wf = __ldg(g_WfT + c * 128 + tid);
            float wh = __ldg(g_WhT + c * 128 + tid);
#pragma unroll
            for (int ii = 0; ii < 8; ii++) {
                int row = ch * 8 + ii;
                float n = nh[row * 128 + c];
                float f = fn[row * 128 + c];
                a[ii] = fmaf(n, wa, a[ii]);
                b[ii] = fmaf(f, wf, fmaf(n, wh, b[ii]));
            }
        }
#pragma unroll
        for (int ii = 0; ii < 8; ii++) {
            g_A[(i0 + ch * 8 + ii) * 128 + tid] = a[ii];
            g_B[(i0 + ch * 8 + ii) * 128 + tid] = b[ii];
        }
    }
}

// ---------------- KNN: one warp per row, 16 rows / 512-thread block ----------------
__global__ void __launch_bounds__(512) knn_kernel(const float* __restrict__ X) {
    extern __shared__ float sx[];   // [3][L] SoA
    int tid = threadIdx.x;
    for (int idx = tid; idx < L; idx += 512) {
        sx[idx]         = X[3 * idx];
        sx[L + idx]     = X[3 * idx + 1];
        sx[2 * L + idx] = X[3 * idx + 2];
    }
    __syncthreads();
    int lane = tid & 31;
    int i = blockIdx.x * 16 + (tid >> 5);
    float xi = sx[i], yi = sx[L + i], zi = sx[2 * L + i];

    ull h[8];
#pragma unroll
    for (int m = 0; m < 8; m++) h[m] = SENTK;

    // initial scan: lane-local sorted top-8 (keys = ssq_bits<<32 | j, unique)
#pragma unroll 4
    for (int s = 0; s < L / 32; s++) {
        int j = lane + (s << 5);
        float dx = xi - sx[j], dy = yi - sx[L + j], dz = zi - sx[2 * L + j];
        float ssq = __fadd_rn(__fadd_rn(__fmul_rn(dx, dx), __fmul_rn(dy, dy)), __fmul_rn(dz, dz));
        unsigned sb = __float_as_uint(ssq);
        unsigned hs = (unsigned)(h[7] >> 32);
        if (sb < hs || (sb == hs && (unsigned)j < (unsigned)h[7])) {
            h[7] = ((ull)sb << 32) | (unsigned)j;
#pragma unroll
            for (int m = 7; m > 0; m--)
                if (h[m] < h[m - 1]) { ull t = h[m]; h[m] = h[m - 1]; h[m - 1] = t; }
        }
    }

    ull mylast = 0ULL;
    for (int r = 0; r < K; r++) {
        if (h[0] == SENTK) {   // rare refill
            for (int s = 0; s < L / 32; s++) {
                int j = lane + (s << 5);
                float dx = xi - sx[j], dy = yi - sx[L + j], dz = zi - sx[2 * L + j];
                float ssq = __fadd_rn(__fadd_rn(__fmul_rn(dx, dx), __fmul_rn(dy, dy)), __fmul_rn(dz, dz));
                ull key = ((ull)__float_as_uint(ssq) << 32) | (unsigned)j;
                if (key > mylast && key < h[7]) {
                    h[7] = key;
#pragma unroll
                    for (int m = 7; m > 0; m--)
                        if (h[m] < h[m - 1]) { ull t = h[m]; h[m] = h[m - 1]; h[m - 1] = t; }
                }
            }
        }
        ull mn = h[0];
#pragma unroll
        for (int off = 16; off > 0; off >>= 1) {
            ull o = __shfl_xor_sync(0xffffffffu, mn, off);
            mn = (o < mn) ? o : mn;
        }
        if (h[0] == mn) {      // unique winner pops & writes
            mylast = mn;
#pragma unroll
            for (int m = 0; m < 7; m++) h[m] = h[m + 1];
            h[7] = SENTK;
            g_knn_idx[i * K + r] = (int)(unsigned)(mn & 0xFFFFFFFFULL);
            float ssq = __uint_as_float((unsigned)(mn >> 32));
            g_knn_d[i * K + r] = sqrtf(ssq + 1e-6f);
        }
    }
}

// ---------------- main: features + packed 32-dim contraction + LN-folded proj ----------------
__global__ void __launch_bounds__(128, 4) main_kernel(const float* __restrict__ X,
                                                      const float* __restrict__ Wpos,
                                                      const float* __restrict__ bpos,
                                                      const int* __restrict__ aatype,
                                                      const int* __restrict__ resi,
                                                      float* __restrict__ out) {
    extern __shared__ float sm[];
    float* sE     = sm;               // 48*132 = 6336  e[k][c], stride 132
    float* sSmall = sm + 6336;        // 48*32  = 1536  [k][q] : e_pos(16)+rbf(16)
    float* sA     = sm + 7872;        // 128
    float* sw1    = sm + 8000;        // 128
    float* sc0    = sm + 8128;        // 128
    float* sMean  = sm + 8256;        // 48
    float* sRstd  = sm + 8304;        // 48
    int*   sJ     = (int*)(sm + 8352);// 48
    float* sD     = sm + 8400;        // 48   total 8448 floats = 33792 B

    int tid = threadIdx.x;
    int i = blockIdx.x;

    {
        if (tid < 32) ((float4*)sA)[tid] = ((const float4*)(g_A + i * 128))[tid];
        sw1[tid] = g_w1[tid];
        sc0[tid] = g_c0[tid];
        if (tid < K) { sJ[tid] = g_knn_idx[i * K + tid]; sD[tid] = g_knn_d[i * K + tid]; }
    }
    __syncthreads();

    // ---- Phase A: per-edge features + e_pos (thread k) ----
    if (tid < K) {
        int k = tid;
        int j = sJ[k];
        float d = sD[k];
        float rb[16];
#pragma unroll
        for (int q = 0; q < 16; q++) {
            float mu = 2.0f + (20.0f / 15.0f) * (float)q;
            float t = (d - mu) * 0.8f;
            rb[q] = expf(-t * t);
            sSmall[k * 32 + 16 + q] = rb[q];
        }
        float gm[8];
        gm[0] = d * 0.1f;
        gm[1] = 1.0f / (1.0f + d);
        gm[2] = expf(-d);
        gm[3] = sinf(d);
        gm[4] = cosf(d);
        float inv = 1.0f / (d + 1e-6f);
        float xs = X[3 * i], ys = X[3 * i + 1], zs = X[3 * i + 2];
        gm[5] = (X[3 * j] - xs) * inv;
        gm[6] = (X[3 * j + 1] - ys) * inv;
        gm[7] = (X[3 * j + 2] - zs) * inv;
        int off = resi[j] - resi[i];
        int p = min(max(off + 8, 0), 15);
        int aa = aatype[j];
#pragma unroll
        for (int r = 0; r < 16; r++) {
            const float* wr = Wpos + r * 66;
            float acc = bpos[r] + __ldg(wr + p) + __ldg(wr + 40 + aa);
#pragma unroll
            for (int q = 0; q < 16; q++) acc = fmaf(rb[q], __ldg(wr + 16 + q), acc);
#pragma unroll
            for (int g = 0; g < 8; g++) acc = fmaf(gm[g], __ldg(wr + 32 + g), acc);
            sSmall[k * 32 + r] = acc;
        }
    }
    __syncthreads();

    // ---- Phase B (f32x2 over q-pairs): e[k][c] = A[c] + B[j_k][c] + small[k,:].w[:,c] ----
    {
        int c = tid;
        ull w2[16];
        const ull* gw2 = (const ull*)(g_Wsm2 + c * 32);
#pragma unroll
        for (int q2 = 0; q2 < 16; q2++) w2[q2] = __ldg(gw2 + q2);
        float a = sA[c];
        for (int k0 = 0; k0 < K; k0 += 4) {
            ull acc[4];
#pragma unroll
            for (int kk = 0; kk < 4; kk++)
                acc[kk] = pack2(a + __ldg(g_B + (size_t)sJ[k0 + kk] * 128 + c), 0.f);
#pragma unroll
            for (int q2 = 0; q2 < 16; q2++) {
#pragma unroll
                for (int kk = 0; kk < 4; kk++) {
                    ull s2 = *(const ull*)(sSmall + (k0 + kk) * 32 + q2 * 2);
                    acc[kk] = fma2(s2, w2[q2], acc[kk]);
                }
            }
#pragma unroll
            for (int kk = 0; kk < 4; kk++)
                sE[(k0 + kk) * 132 + c] = lo2(acc[kk]) + hi2(acc[kk]);
        }
    }
    __syncthreads();

    // ---- LN stats: warp-parallel over k ----
    {
        int wrp = tid >> 5, lane = tid & 31;
        for (int k = wrp; k < K; k += 4) {
            float s = 0.f, ss = 0.f;
#pragma unroll
            for (int q = 0; q < 4; q++) {
                float v = sE[k * 132 + lane + q * 32];
                s += v;
                ss = fmaf(v, v, ss);
            }
#pragma unroll
            for (int off = 16; off > 0; off >>= 1) {
                s += __shfl_xor_sync(0xffffffffu, s, off);
                ss += __shfl_xor_sync(0xffffffffu, ss, off);
            }
            if (lane == 0) {
                float mean = s * (1.0f / 128.0f);
                float var = ss * (1.0f / 128.0f) - mean * mean;
                sMean[k] = mean;
                sRstd[k] = rsqrtf(var + 1e-5f);
            }
        }
    }
    __syncthreads();

    // ---- Phase C: projection GEMM, 6k x (4 f32x2) register tile ----
    {
        int kg = tid >> 4;       // 0..7
        int ng = tid & 15;       // 0..15
        int k0 = kg * 6;
        int n0 = ng * 8;
        ull acc[6][4];
#pragma unroll
        for (int kk = 0; kk < 6; kk++)
#pragma unroll
            for (int p = 0; p < 4; p++) acc[kk][p] = 0ULL;

#pragma unroll 2
        for (int c = 0; c < 128; c++) {
            const ulonglong2* wp = (const ulonglong2*)(g_WpT + c * 128 + n0);
            ulonglong2 wa = __ldg(wp);
            ulonglong2 wb = __ldg(wp + 1);
#pragma unroll
            for (int kk = 0; kk < 6; kk++) {
                float e = sE[(k0 + kk) * 132 + c];
                ull e2 = pack2(e, e);
                acc[kk][0] = fma2(e2, wa.x, acc[kk][0]);
                acc[kk][1] = fma2(e2, wa.y, acc[kk][1]);
                acc[kk][2] = fma2(e2, wb.x, acc[kk][2]);
                acc[kk][3] = fma2(e2, wb.y, acc[kk][3]);
            }
        }
#pragma unroll
        for (int kk = 0; kk < 6; kk++) {
            int k = k0 + kk;
            float mean = sMean[k], rstd = sRstd[k];
            float o[8];
#pragma unroll
            for (int p = 0; p < 4; p++) {
                o[2 * p]     = fmaf(rstd, lo2(acc[kk][p]) - mean * sw1[n0 + 2 * p],     sc0[n0 + 2 * p]);
                o[2 * p + 1] = fmaf(rstd, hi2(acc[kk][p]) - mean * sw1[n0 + 2 * p + 1], sc0[n0 + 2 * p + 1]);
            }
            float* op = out + ((size_t)i * K + k) * 128 + n0;
            *(float4*)op       = make_float4(o[0], o[1], o[2], o[3]);
            *(float4*)(op + 4) = make_float4(o[4], o[5], o[6], o[7]);
        }
    }
}

// ---------------- launch ----------------
extern "C" void kernel_launch(void* const* d_in, const int* in_sizes, int n_in,
                              void* d_out, int out_size) {
    const float* X        = (const float*)d_in[0];
    const float* node_h   = (const float*)d_in[1];
    const float* f_node   = (const float*)d_in[2];
    const float* Wpos     = (const float*)d_in[3];
    const float* bpos     = (const float*)d_in[4];
    const float* We       = (const float*)d_in[5];
    const float* ln_scale = (const float*)d_in[6];
    const float* ln_bias  = (const float*)d_in[7];
    const float* Wproj    = (const float*)d_in[8];
    const float* bproj    = (const float*)d_in[9];
    const int*   aatype   = (const int*)d_in[10];
    const int*   resi     = (const int*)d_in[11];
    float* out = (float*)d_out;

    cudaFuncSetAttribute(knn_kernel, cudaFuncAttributeMaxDynamicSharedMemorySize, 3 * L * 4);
    cudaFuncSetAttribute(main_kernel, cudaFuncAttributeMaxDynamicSharedMemorySize, 33792);

    prep_small_kernel<<<32, 256>>>(Wproj, ln_scale, ln_bias, bproj, We);
    prep_ab_kernel<<<L / 32, 128>>>(node_h, f_node);
    knn_kernel<<<L / 16, 512, 3 * L * 4>>>(X);
    main_kernel<<<L, 128, 33792>>>(X, Wpos, bpos, aatype, resi, out);
}

// round 7
// speedup vs baseline: 1.5758x; 1.1952x over previous
#include <cuda_runtime.h>
#include <cuda_bf16.h>
#include <cstdint>
#include <math.h>

#define L 8192
#define K 48
#define SENTK 0xFFFFFFFFFFFFFFFFULL
typedef unsigned long long ull;

#define M_EDGES (L * K)          // 393216
#define N_TILES (M_EDGES / 128)  // 3072

// ---------------- device scratch (static; allocation-free) ----------------
__device__ __align__(16) float g_A[L * 128];
__device__ __align__(16) float g_B[L * 128];
__device__ __align__(16) float g_Wsm2[128 * 32];        // [c][q] = We[c][128+q]
__device__ __align__(16) float g_WAT[128 * 128];
__device__ __align__(16) float g_WfT[128 * 128];
__device__ __align__(16) float g_WhT[128 * 128];
__device__ __align__(16) float g_w1[128];
__device__ __align__(16) float g_c0[128];
__device__ __align__(16) __nv_bfloat16 g_WT_hi[128 * 128]; // [n][c] bf16 hi of Wproj[n][c]*ln_scale[c]
__device__ __align__(16) __nv_bfloat16 g_WT_lo[128 * 128]; // residual
__device__ int   g_knn_idx[L * K];
__device__ float g_knn_d[L * K];
__device__ __align__(16) float g_E[(size_t)M_EDGES * 128]; // pre-LN edge features
__device__ float g_mean[M_EDGES];
__device__ float g_rstd[M_EDGES];

// ---------------- f32x2 helpers ----------------
__device__ __forceinline__ ull fma2(ull a, ull b, ull c) {
    ull d;
    asm("fma.rn.f32x2 %0, %1, %2, %3;" : "=l"(d) : "l"(a), "l"(b), "l"(c));
    return d;
}
__device__ __forceinline__ ull pack2(float lo, float hi) {
    ull d;
    asm("mov.b64 %0, {%1, %2};" : "=l"(d) : "r"(__float_as_uint(lo)), "r"(__float_as_uint(hi)));
    return d;
}
__device__ __forceinline__ float lo2(ull v) { return __uint_as_float((unsigned)v); }
__device__ __forceinline__ float hi2(ull v) { return __uint_as_float((unsigned)(v >> 32)); }

__device__ __forceinline__ uint32_t smem_u32(const void* p) {
    uint32_t a;
    asm("{ .reg .u64 t; cvta.to.shared.u64 t, %1; cvt.u32.u64 %0, t; }" : "=r"(a) : "l"(p));
    return a;
}
__device__ __forceinline__ uint32_t bf2u(__nv_bfloat162 v) {
    uint32_t u;
    u = *reinterpret_cast<uint32_t*>(&v);
    return u;
}

// ---------------- mma.sync / ldmatrix helpers (base sm_103 target legal) ----------------
__device__ __forceinline__ void ldm4(uint32_t* r, uint32_t addr) {
    asm volatile("ldmatrix.sync.aligned.m8n8.x4.shared.b16 {%0,%1,%2,%3}, [%4];"
                 : "=r"(r[0]), "=r"(r[1]), "=r"(r[2]), "=r"(r[3]) : "r"(addr));
}
__device__ __forceinline__ void mma_bf16(float* c, const uint32_t* a, const uint32_t* b) {
    asm volatile("mma.sync.aligned.m16n8k16.row.col.f32.bf16.bf16.f32 "
                 "{%0,%1,%2,%3}, {%4,%5,%6,%7}, {%8,%9}, {%0,%1,%2,%3};"
                 : "+f"(c[0]), "+f"(c[1]), "+f"(c[2]), "+f"(c[3])
                 : "r"(a[0]), "r"(a[1]), "r"(a[2]), "r"(a[3]), "r"(b[0]), "r"(b[1]));
}

// ---------------- tiny precompute ----------------
__global__ void prep_small_kernel(const float* __restrict__ Wproj,
                                  const float* __restrict__ ln_scale,
                                  const float* __restrict__ ln_bias,
                                  const float* __restrict__ bproj,
                                  const float* __restrict__ We) {
    int gid = blockIdx.x * blockDim.x + threadIdx.x;
    int NT = gridDim.x * blockDim.x;
    for (int n = gid; n < 16384; n += NT) {
        int c = n >> 7, t = n & 127;
        g_WAT[n] = We[t * 416 + 160 + c];
        g_WfT[n] = We[t * 416 + c];
        g_WhT[n] = We[t * 416 + 288 + c];
        int tt = n >> 7, cc = n & 127;
        float w = Wproj[tt * 128 + cc] * ln_scale[cc];
        __nv_bfloat16 h = __float2bfloat16(w);
        float res = w - __bfloat162float(h);
        g_WT_hi[n] = h;
        g_WT_lo[n] = __float2bfloat16(res);
    }
    for (int n = gid; n < 4096; n += NT) {
        int c = n >> 5, q = n & 31;
        g_Wsm2[n] = We[c * 416 + 128 + q];
    }
    if (gid < 128) {
        float s1 = 0.f, s0 = 0.f;
        for (int c = 0; c < 128; c++) {
            float w = Wproj[gid * 128 + c];
            s1 += w * ln_scale[c];
            s0 += w * ln_bias[c];
        }
        g_w1[gid] = s1;
        g_c0[gid] = s0 + bproj[gid];
    }
}

// ---------------- A/B tables ----------------
__global__ void __launch_bounds__(128) prep_ab_kernel(const float* __restrict__ node_h,
                                                      const float* __restrict__ f_node) {
    __shared__ float nh[32 * 128];
    __shared__ float fn[32 * 128];
    int tid = threadIdx.x;
    int i0 = blockIdx.x * 32;
    for (int f = tid; f < 32 * 128; f += 128) {
        nh[f] = node_h[i0 * 128 + f];
        fn[f] = f_node[i0 * 128 + f];
    }
    __syncthreads();
    for (int ch = 0; ch < 4; ch++) {
        float a[8], b[8];
#pragma unroll
        for (int ii = 0; ii < 8; ii++) { a[ii] = 0.f; b[ii] = 0.f; }
#pragma unroll 4
        for (int c = 0; c < 128; c++) {
            float wa = __ldg(g_WAT + c * 128 + tid);
            float wf = __ldg(g_WfT + c * 128 + tid);
            float wh = __ldg(g_WhT + c * 128 + tid);
#pragma unroll
            for (int ii = 0; ii < 8; ii++) {
                int row = ch * 8 + ii;
                float n = nh[row * 128 + c];
                float f = fn[row * 128 + c];
                a[ii] = fmaf(n, wa, a[ii]);
                b[ii] = fmaf(f, wf, fmaf(n, wh, b[ii]));
            }
        }
#pragma unroll
        for (int ii = 0; ii < 8; ii++) {
            g_A[(i0 + ch * 8 + ii) * 128 + tid] = a[ii];
            g_B[(i0 + ch * 8 + ii) * 128 + tid] = b[ii];
        }
    }
}

// ---------------- KNN (unchanged, passing) ----------------
__global__ void __launch_bounds__(512) knn_kernel(const float* __restrict__ X) {
    extern __shared__ float sx[];
    int tid = threadIdx.x;
    for (int idx = tid; idx < L; idx += 512) {
        sx[idx]         = X[3 * idx];
        sx[L + idx]     = X[3 * idx + 1];
        sx[2 * L + idx] = X[3 * idx + 2];
    }
    __syncthreads();
    int lane = tid & 31;
    int i = blockIdx.x * 16 + (tid >> 5);
    float xi = sx[i], yi = sx[L + i], zi = sx[2 * L + i];

    ull h[8];
#pragma unroll
    for (int m = 0; m < 8; m++) h[m] = SENTK;

#pragma unroll 4
    for (int s = 0; s < L / 32; s++) {
        int j = lane + (s << 5);
        float dx = xi - sx[j], dy = yi - sx[L + j], dz = zi - sx[2 * L + j];
        float ssq = __fadd_rn(__fadd_rn(__fmul_rn(dx, dx), __fmul_rn(dy, dy)), __fmul_rn(dz, dz));
        unsigned sb = __float_as_uint(ssq);
        unsigned hs = (unsigned)(h[7] >> 32);
        if (sb < hs || (sb == hs && (unsigned)j < (unsigned)h[7])) {
            h[7] = ((ull)sb << 32) | (unsigned)j;
#pragma unroll
            for (int m = 7; m > 0; m--)
                if (h[m] < h[m - 1]) { ull t = h[m]; h[m] = h[m - 1]; h[m - 1] = t; }
        }
    }

    ull mylast = 0ULL;
    for (int r = 0; r < K; r++) {
        if (h[0] == SENTK) {
            for (int s = 0; s < L / 32; s++) {
                int j = lane + (s << 5);
                float dx = xi - sx[j], dy = yi - sx[L + j], dz = zi - sx[2 * L + j];
                float ssq = __fadd_rn(__fadd_rn(__fmul_rn(dx, dx), __fmul_rn(dy, dy)), __fmul_rn(dz, dz));
                ull key = ((ull)__float_as_uint(ssq) << 32) | (unsigned)j;
                if (key > mylast && key < h[7]) {
                    h[7] = key;
#pragma unroll
                    for (int m = 7; m > 0; m--)
                        if (h[m] < h[m - 1]) { ull t = h[m]; h[m] = h[m - 1]; h[m - 1] = t; }
                }
            }
        }
        ull mn = h[0];
#pragma unroll
        for (int off = 16; off > 0; off >>= 1) {
            ull o = __shfl_xor_sync(0xffffffffu, mn, off);
            mn = (o < mn) ? o : mn;
        }
        if (h[0] == mn) {
            mylast = mn;
#pragma unroll
            for (int m = 0; m < 7; m++) h[m] = h[m + 1];
            h[7] = SENTK;
            g_knn_idx[i * K + r] = (int)(unsigned)(mn & 0xFFFFFFFFULL);
            float ssq = __uint_as_float((unsigned)(mn >> 32));
            g_knn_d[i * K + r] = sqrtf(ssq + 1e-6f);
        }
    }
}

// ---------------- features: phases A+B + LN stats -> g_E, g_mean, g_rstd ----------------
__global__ void __launch_bounds__(128, 4) features_kernel(const float* __restrict__ X,
                                                          const float* __restrict__ Wpos,
                                                          const float* __restrict__ bpos,
                                                          const int* __restrict__ aatype,
                                                          const int* __restrict__ resi) {
    extern __shared__ float sm[];
    float* sE     = sm;                // 48*132
    float* sSmall = sm + 6336;         // 48*32
    float* sA     = sm + 7872;         // 128
    float* sMean  = sm + 8000;         // 48
    float* sRstd  = sm + 8048;         // 48
    int*   sJ     = (int*)(sm + 8096); // 48
    float* sD     = sm + 8144;         // 48

    int tid = threadIdx.x;
    int i = blockIdx.x;

    if (tid < 32) ((float4*)sA)[tid] = ((const float4*)(g_A + i * 128))[tid];
    if (tid < K) { sJ[tid] = g_knn_idx[i * K + tid]; sD[tid] = g_knn_d[i * K + tid]; }
    __syncthreads();

    if (tid < K) {
        int k = tid;
        int j = sJ[k];
        float d = sD[k];
        float rb[16];
#pragma unroll
        for (int q = 0; q < 16; q++) {
            float mu = 2.0f + (20.0f / 15.0f) * (float)q;
            float t = (d - mu) * 0.8f;
            rb[q] = expf(-t * t);
            sSmall[k * 32 + 16 + q] = rb[q];
        }
        float gm[8];
        gm[0] = d * 0.1f;
        gm[1] = 1.0f / (1.0f + d);
        gm[2] = expf(-d);
        gm[3] = sinf(d);
        gm[4] = cosf(d);
        float inv = 1.0f / (d + 1e-6f);
        float xs = X[3 * i], ys = X[3 * i + 1], zs = X[3 * i + 2];
        gm[5] = (X[3 * j] - xs) * inv;
        gm[6] = (X[3 * j + 1] - ys) * inv;
        gm[7] = (X[3 * j + 2] - zs) * inv;
        int off = resi[j] - resi[i];
        int p = min(max(off + 8, 0), 15);
        int aa = aatype[j];
#pragma unroll
        for (int r = 0; r < 16; r++) {
            const float* wr = Wpos + r * 66;
            float acc = bpos[r] + __ldg(wr + p) + __ldg(wr + 40 + aa);
#pragma unroll
            for (int q = 0; q < 16; q++) acc = fmaf(rb[q], __ldg(wr + 16 + q), acc);
#pragma unroll
            for (int g = 0; g < 8; g++) acc = fmaf(gm[g], __ldg(wr + 32 + g), acc);
            sSmall[k * 32 + r] = acc;
        }
    }
    __syncthreads();

    {
        int c = tid;
        ull w2[16];
        const ull* gw2 = (const ull*)(g_Wsm2 + c * 32);
#pragma unroll
        for (int q2 = 0; q2 < 16; q2++) w2[q2] = __ldg(gw2 + q2);
        float a = sA[c];
        for (int k0 = 0; k0 < K; k0 += 4) {
            ull acc[4];
#pragma unroll
            for (int kk = 0; kk < 4; kk++)
                acc[kk] = pack2(a + __ldg(g_B + (size_t)sJ[k0 + kk] * 128 + c), 0.f);
#pragma unroll
            for (int q2 = 0; q2 < 16; q2++) {
#pragma unroll
                for (int kk = 0; kk < 4; kk++) {
                    ull s2 = *(const ull*)(sSmall + (k0 + kk) * 32 + q2 * 2);
                    acc[kk] = fma2(s2, w2[q2], acc[kk]);
                }
            }
#pragma unroll
            for (int kk = 0; kk < 4; kk++)
                sE[(k0 + kk) * 132 + c] = lo2(acc[kk]) + hi2(acc[kk]);
        }
    }
    __syncthreads();

    {
        int wrp = tid >> 5, lane = tid & 31;
        for (int k = wrp; k < K; k += 4) {
            float s = 0.f, ss = 0.f;
#pragma unroll
            for (int q = 0; q < 4; q++) {
                float v = sE[k * 132 + lane + q * 32];
                s += v;
                ss = fmaf(v, v, ss);
            }
#pragma unroll
            for (int off = 16; off > 0; off >>= 1) {
                s += __shfl_xor_sync(0xffffffffu, s, off);
                ss += __shfl_xor_sync(0xffffffffu, ss, off);
            }
            if (lane == 0) {
                float mean = s * (1.0f / 128.0f);
                float var = ss * (1.0f / 128.0f) - mean * mean;
                sMean[k] = mean;
                sRstd[k] = rsqrtf(var + 1e-5f);
            }
        }
    }
    __syncthreads();

    {
        size_t base = (size_t)i * K * 128;
#pragma unroll 4
        for (int k = 0; k < K; k++)
            g_E[base + (size_t)k * 128 + tid] = sE[k * 132 + tid];
        if (tid < K) {
            g_mean[i * K + tid] = sMean[tid];
            g_rstd[i * K + tid] = sRstd[tid];
        }
    }
}

// ---------------- projection GEMM: mma.sync bf16 3-term split ----------------
// smem layout (bf16, stride 136 elems = 272 B -> ldmatrix conflict-free)
#define SSTR 136
#define EHI_OFF 0
#define ELO_OFF (128 * SSTR * 2)          // 34816
#define WHI_OFF (2 * 128 * SSTR * 2)      // 69632
#define WLO_OFF (3 * 128 * SSTR * 2)      // 104448
#define GEMM_SMEM (4 * 128 * SSTR * 2)    // 139264

__global__ void __launch_bounds__(256, 1) proj_gemm_kernel(float* __restrict__ out) {
    extern __shared__ __align__(16) char gsm[];
    uint32_t sb = smem_u32(gsm);
    int tid = threadIdx.x;
    int wid = tid >> 5, lane = tid & 31;
    int m0 = blockIdx.x * 128;

    // ---- stage W hi/lo (bf16, row-major [n][k]) ----
#pragma unroll
    for (int it = 0; it < 8; it++) {
        int vec = it * 256 + tid;           // uint4 = 8 bf16
        int n = vec >> 4;
        int c8 = (vec & 15) << 3;
        uint32_t so = (uint32_t)n * (SSTR * 2) + c8 * 2;
        *(uint4*)(gsm + WHI_OFF + so) = __ldg((const uint4*)(g_WT_hi + (size_t)n * 128 + c8));
        *(uint4*)(gsm + WLO_OFF + so) = __ldg((const uint4*)(g_WT_lo + (size_t)n * 128 + c8));
    }
    // ---- stage E fp32 -> bf16 hi/lo ----
#pragma unroll
    for (int it = 0; it < 16; it++) {
        int vec = it * 256 + tid;           // float4 = 4 fp32
        int r = vec >> 5;
        int c4 = (vec & 31) << 2;
        float4 e4 = __ldg((const float4*)(g_E + ((size_t)(m0 + r) << 7) + c4));
        __nv_bfloat162 h0 = __float22bfloat162_rn(make_float2(e4.x, e4.y));
        __nv_bfloat162 h1 = __float22bfloat162_rn(make_float2(e4.z, e4.w));
        float2 f0 = __bfloat1622float2(h0);
        float2 f1 = __bfloat1622float2(h1);
        __nv_bfloat162 l0 = __float22bfloat162_rn(make_float2(e4.x - f0.x, e4.y - f0.y));
        __nv_bfloat162 l1 = __float22bfloat162_rn(make_float2(e4.z - f1.x, e4.w - f1.y));
        uint32_t so = (uint32_t)r * (SSTR * 2) + c4 * 2;
        *(uint2*)(gsm + EHI_OFF + so) = make_uint2(bf2u(h0), bf2u(h1));
        *(uint2*)(gsm + ELO_OFF + so) = make_uint2(bf2u(l0), bf2u(l1));
    }
    __syncthreads();

    // ---- warp tiles: 2 m-groups x 4 n-groups; each warp 64m x 32n ----
    int m_base = (wid >> 2) * 64;
    int n_base = (wid & 3) * 32;
    int g = lane >> 3, ri = lane & 7;

    uint32_t aoff[4], boff[2];
#pragma unroll
    for (int mf = 0; mf < 4; mf++)
        aoff[mf] = (uint32_t)((m_base + mf * 16 + ri + (g & 1) * 8) * SSTR + (g >> 1) * 8) * 2;
#pragma unroll
    for (int nb = 0; nb < 2; nb++)
        boff[nb] = (uint32_t)((n_base + nb * 16 + ri + (g >> 1) * 8) * SSTR + (g & 1) * 8) * 2;

    float acc[4][4][4];
#pragma unroll
    for (int mf = 0; mf < 4; mf++)
#pragma unroll
        for (int nf = 0; nf < 4; nf++)
#pragma unroll
            for (int q = 0; q < 4; q++) acc[mf][nf][q] = 0.f;

#pragma unroll
    for (int ks = 0; ks < 8; ks++) {
        uint32_t kb = ks * 32;
        uint32_t ah[4][4], al[4][4], bh[2][4], bl[2][4];
#pragma unroll
        for (int mf = 0; mf < 4; mf++) {
            ldm4(ah[mf], sb + EHI_OFF + aoff[mf] + kb);
            ldm4(al[mf], sb + ELO_OFF + aoff[mf] + kb);
        }
#pragma unroll
        for (int nb = 0; nb < 2; nb++) {
            ldm4(bh[nb], sb + WHI_OFF + boff[nb] + kb);
            ldm4(bl[nb], sb + WLO_OFF + boff[nb] + kb);
        }
#pragma unroll
        for (int mf = 0; mf < 4; mf++) {
#pragma unroll
            for (int nf = 0; nf < 4; nf++) {
                const uint32_t* bhp = &bh[nf >> 1][(nf & 1) * 2];
                const uint32_t* blp = &bl[nf >> 1][(nf & 1) * 2];
                mma_bf16(acc[mf][nf], ah[mf], bhp);
                mma_bf16(acc[mf][nf], ah[mf], blp);
                mma_bf16(acc[mf][nf], al[mf], bhp);
            }
        }
    }

    // ---- epilogue: LN fold + store ----
#pragma unroll
    for (int mf = 0; mf < 4; mf++) {
        int r0 = m0 + m_base + mf * 16 + (lane >> 2);
        float mean0 = __ldg(g_mean + r0), rstd0 = __ldg(g_rstd + r0);
        float mean1 = __ldg(g_mean + r0 + 8), rstd1 = __ldg(g_rstd + r0 + 8);
#pragma unroll
        for (int nf = 0; nf < 4; nf++) {
            int col = n_base + nf * 8 + (lane & 3) * 2;
            float2 w1v = *(const float2*)(g_w1 + col);
            float2 c0v = *(const float2*)(g_c0 + col);
            float2 o0, o1;
            o0.x = fmaf(rstd0, acc[mf][nf][0] - mean0 * w1v.x, c0v.x);
            o0.y = fmaf(rstd0, acc[mf][nf][1] - mean0 * w1v.y, c0v.y);
            o1.x = fmaf(rstd1, acc[mf][nf][2] - mean1 * w1v.x, c0v.x);
            o1.y = fmaf(rstd1, acc[mf][nf][3] - mean1 * w1v.y, c0v.y);
            *(float2*)(out + (size_t)r0 * 128 + col) = o0;
            *(float2*)(out + (size_t)(r0 + 8) * 128 + col) = o1;
        }
    }
}

// ---------------- launch ----------------
extern "C" void kernel_launch(void* const* d_in, const int* in_sizes, int n_in,
                              void* d_out, int out_size) {
    const float* X        = (const float*)d_in[0];
    const float* node_h   = (const float*)d_in[1];
    const float* f_node   = (const float*)d_in[2];
    const float* Wpos     = (const float*)d_in[3];
    const float* bpos     = (const float*)d_in[4];
    const float* We       = (const float*)d_in[5];
    const float* ln_scale = (const float*)d_in[6];
    const float* ln_bias  = (const float*)d_in[7];
    const float* Wproj    = (const float*)d_in[8];
    const float* bproj    = (const float*)d_in[9];
    const int*   aatype   = (const int*)d_in[10];
    const int*   resi     = (const int*)d_in[11];
    float* out = (float*)d_out;

    cudaFuncSetAttribute(knn_kernel, cudaFuncAttributeMaxDynamicSharedMemorySize, 3 * L * 4);
    cudaFuncSetAttribute(features_kernel, cudaFuncAttributeMaxDynamicSharedMemorySize, 32768);
    cudaFuncSetAttribute(proj_gemm_kernel, cudaFuncAttributeMaxDynamicSharedMemorySize, GEMM_SMEM);

    prep_small_kernel<<<32, 256>>>(Wproj, ln_scale, ln_bias, bproj, We);
    prep_ab_kernel<<<L / 32, 128>>>(node_h, f_node);
    knn_kernel<<<L / 16, 512, 3 * L * 4>>>(X);
    features_kernel<<<L, 128, 32768>>>(X, Wpos, bpos, aatype, resi);
    proj_gemm_kernel<<<N_TILES, 256, GEMM_SMEM>>>(out);
}